// round 5
// baseline (speedup 1.0000x reference)
#include <cuda_runtime.h>
#include <cstdint>

// ---------------------------------------------------------------------------
// PConvLinear via mma.sync tf32 (m16n8k8), pipelined staging.
//   out[p,o] = bias[o] + sum_f P[p,f] * W[o,f]
//   P[p, c*16+m] = sum_{k<16} feat[p,k,c] * wn[p,k,m]
// Block: 512 threads, 128 points x 128 outputs, 34 chunks of 32 f.
// wn register-resident; gather double-buffered (hidden behind compute);
// W prefetched one chunk ahead; one __syncthreads per chunk.
// ---------------------------------------------------------------------------

#define NPTS 120000
#define NB   60000
#define TPB  128
#define THREADS 512
#define GRID ((NPTS + TPB - 1) / TPB)   // 938
#define NCHUNK 34

#define TSTRIDE 36                 // padded float stride of tf32 tiles
#define TILE_FL (128 * TSTRIDE)    // 4608 floats per tile buffer
#define GS_FL   16384              // one gather buffer: 8ch x 16k x 128p

// smem layout (float offsets)
#define OFF_WT   0                        // 2 x 4608  W tf32 [o][f]
#define OFF_PT   (2 * TILE_FL)            // 2 x 4608  P tf32 [p][f]
#define OFF_G    (4 * TILE_FL)            // 2 x 16384 gathered feats
#define OFF_I    (4 * TILE_FL + 2 * GS_FL)// 2048 ints neighbor inds
#define OFF_BIAS (OFF_I + 2048)           // 128
#define SMEM_FLOATS (OFF_BIAS + 128)
#define SMEM_BYTES (SMEM_FLOATS * 4)      // 213,504 B

__device__ __forceinline__ uint32_t smem_u32(const void* p) {
    uint32_t a;
    asm("{ .reg .u64 t; cvta.to.shared.u64 t, %1; cvt.u32.u64 %0, t; }"
        : "=r"(a) : "l"(p));
    return a;
}
__device__ __forceinline__ uint32_t cvt_tf32(float f) {
    uint32_t r; asm("cvt.rna.tf32.f32 %0, %1;" : "=r"(r) : "f"(f)); return r;
}
__device__ __forceinline__ unsigned long long pack2(float lo, float hi) {
    unsigned long long r;
    asm("mov.b64 %0, {%1, %2};" : "=l"(r) : "f"(lo), "f"(hi));
    return r;
}
__device__ __forceinline__ void unpack2(unsigned long long v, float& lo, float& hi) {
    asm("mov.b64 {%0, %1}, %2;" : "=f"(lo), "=f"(hi) : "l"(v));
}
__device__ __forceinline__ void fma2(unsigned long long& d,
                                     unsigned long long a, unsigned long long b) {
    asm("fma.rn.f32x2 %0, %1, %2, %0;" : "+l"(d) : "l"(a), "l"(b));
}
__device__ __forceinline__ void ldsm4(uint32_t r[4], uint32_t addr) {
    asm volatile("ldmatrix.sync.aligned.m8n8.x4.shared.b16 {%0,%1,%2,%3}, [%4];"
                 : "=r"(r[0]), "=r"(r[1]), "=r"(r[2]), "=r"(r[3]) : "r"(addr));
}
__device__ __forceinline__ void mma8(float c[4], const uint32_t a[4],
                                     uint32_t b0, uint32_t b1) {
    asm volatile(
        "mma.sync.aligned.m16n8k8.row.col.f32.tf32.tf32.f32 "
        "{%0,%1,%2,%3}, {%4,%5,%6,%7}, {%8,%9}, {%0,%1,%2,%3};"
        : "+f"(c[0]), "+f"(c[1]), "+f"(c[2]), "+f"(c[3])
        : "r"(a[0]), "r"(a[1]), "r"(a[2]), "r"(a[3]), "r"(b0), "r"(b1));
}

extern "C" __global__ void __launch_bounds__(THREADS, 1)
pcl_kernel(const float* __restrict__ xin,   // [2,60000,64]
           const int*   __restrict__ nbr,   // [2,60000,16]
           const float* __restrict__ wng,   // [2,60000,16,16]
           const float* __restrict__ addf,  // [2,60000,16,3]
           const float* __restrict__ W,     // [128,1072]
           const float* __restrict__ bias,  // [128]
           float*       __restrict__ out)   // [2,60000,128]
{
    extern __shared__ __align__(16) float sm[];
    int* inds = (int*)(sm + OFF_I);

    const uint32_t smb = smem_u32(sm);
    const int t    = threadIdx.x;
    const int wid  = t >> 5;
    const int l    = t & 31;
    const int base = blockIdx.x * TPB;
    const int p    = t & 127;          // P-compute: point
    const int mq   = t >> 7;           // P-compute: m-quad (4 m)

    // MMA roles: warp grid 4(m) x 4(n); each warp 32p x 32o
    const int wm  = wid & 3;
    const int wn  = wid >> 2;
    const uint32_t aBase = smb + (uint32_t)(OFF_PT + (wm * 32 + (l & 15)) * TSTRIDE
                                            + ((l & 16) ? 4 : 0)) * 4;
    const uint32_t bBase = smb + (uint32_t)(OFF_WT + (wn * 32 + (l & 7)
                                            + ((l & 16) ? 8 : 0)) * TSTRIDE
                                            + ((l & 8) ? 4 : 0)) * 4;

    if (t < 128) sm[OFF_BIAS + t] = bias[t];

    // ---- neighbor indices ----
    {
        int pp = t >> 2;
        int pt = base + pp;
        int4 v = make_int4(0, 0, 0, 0);
        if (pt < NPTS)
            v = *(const int4*)(nbr + (size_t)pt * 16 + (size_t)(t & 3) * 4);
        ((int4*)inds)[t] = v;
    }

    // ---- stage wn (two halves through gs buffer 0), load into registers ----
    unsigned long long wn2[16][2];
    {
        float* scratch = sm + OFF_G;
        #pragma unroll
        for (int h = 0; h < 2; ++h) {
            __syncthreads();
            #pragma unroll
            for (int rep = 0; rep < 8; ++rep) {
                int lin = rep * 2048 + t * 4;
                int pp  = lin >> 7;
                int r   = lin & 127;
                int pid = base + pp; if (pid > NPTS - 1) pid = NPTS - 1;
                float4 v = *(const float4*)(wng + (size_t)pid * 256 + h * 128 + r);
                scratch[(r + 0) * 128 + pp] = v.x;
                scratch[(r + 1) * 128 + pp] = v.y;
                scratch[(r + 2) * 128 + pp] = v.z;
                scratch[(r + 3) * 128 + pp] = v.w;
            }
            __syncthreads();
            #pragma unroll
            for (int k = 0; k < 8; ++k)
                #pragma unroll
                for (int j2 = 0; j2 < 2; ++j2) {
                    float lo = scratch[(k * 16 + mq * 4 + j2 * 2 + 0) * 128 + p];
                    float hi = scratch[(k * 16 + mq * 4 + j2 * 2 + 1) * 128 + p];
                    wn2[h * 8 + k][j2] = pack2(lo, hi);
                }
        }
    }
    __syncthreads();

    // gather-staging thread roles (fixed)
    const int gpp = t & 127;
    const int gkk = t >> 7;            // k-quad start: gkk, gkk+4, gkk+8, gkk+12
    const int gpid = (base + gpp > NPTS - 1) ? NPTS - 1 : base + gpp;
    const int gbrow = (gpid >= NB) ? NB : 0;

    // ---- gather one gidx group into gs buffer gbuf ----
    auto gather = [&](int gidx, int gbuf) {
        float* gsp = sm + OFF_G + gbuf * GS_FL;
        #pragma unroll
        for (int rep = 0; rep < 4; ++rep) {
            int kk = gkk + rep * 4;
            if (gidx < 8) {
                int nb = inds[gpp * 16 + kk];
                const float4* src =
                    (const float4*)(xin + ((size_t)gbrow + nb) * 64 + gidx * 8);
                float4 a = src[0], b4 = src[1];
                gsp[(0 * 16 + kk) * 128 + gpp] = a.x;
                gsp[(1 * 16 + kk) * 128 + gpp] = a.y;
                gsp[(2 * 16 + kk) * 128 + gpp] = a.z;
                gsp[(3 * 16 + kk) * 128 + gpp] = a.w;
                gsp[(4 * 16 + kk) * 128 + gpp] = b4.x;
                gsp[(5 * 16 + kk) * 128 + gpp] = b4.y;
                gsp[(6 * 16 + kk) * 128 + gpp] = b4.z;
                gsp[(7 * 16 + kk) * 128 + gpp] = b4.w;
            } else {
                const float* a = addf + ((size_t)gpid * 16 + kk) * 3;
                gsp[(0 * 16 + kk) * 128 + gpp] = a[0];
                gsp[(1 * 16 + kk) * 128 + gpp] = a[1];
                gsp[(2 * 16 + kk) * 128 + gpp] = a[2];
                gsp[(3 * 16 + kk) * 128 + gpp] = 0.f;
            }
        }
    };

    float acc[2][4][4];
    #pragma unroll
    for (int i = 0; i < 2; ++i)
        #pragma unroll
        for (int j = 0; j < 4; ++j)
            #pragma unroll
            for (int q = 0; q < 4; ++q) acc[i][j][q] = 0.f;

    const int ow = t >> 2;              // W staging: output row
    const int fq = (t & 3) * 8;         // W staging: f offset (8 floats)

    // W prefetch helper
    auto loadW = [&](int cg, float4 wv[2]) {
        int f0 = cg * 32;
        #pragma unroll
        for (int j = 0; j < 2; ++j) {
            int f = f0 + fq + j * 4;
            wv[j] = (f < 1072)
                ? *(const float4*)(W + (size_t)ow * 1072 + f)
                : make_float4(0.f, 0.f, 0.f, 0.f);
        }
    };

    // ---- prologue: gather gidx 0, prefetch W chunk 0 ----
    gather(0, 0);
    float4 wv[2];
    loadW(0, wv);
    __syncthreads();

    int cg = 0;
    for (int gidx = 0; gidx < 9; ++gidx) {
        const int gbuf = gidx & 1;
        float* gsp = sm + OFF_G + gbuf * GS_FL;
        const int ncl = (gidx < 8) ? 4 : 2;

        for (int cl2 = 0; cl2 < ncl; ++cl2, ++cg) {
            const int buf = cg & 1;
            float* Wb = sm + OFF_WT + buf * TILE_FL;
            float* Pb = sm + OFF_PT + buf * TILE_FL;
            const uint32_t bufoff = (uint32_t)(buf * TILE_FL) * 4;

            // ---- P compute: 2 channels x 4 m over 16 k (regs) ----
            #pragma unroll
            for (int cl = 0; cl < 2; ++cl) {
                int gb = ((cl2 * 2 + cl) * 16) * 128 + p;
                unsigned long long a0 = 0, a1 = 0;
                #pragma unroll
                for (int k = 0; k < 16; ++k) {
                    float gv = gsp[gb + k * 128];
                    unsigned long long g2 = pack2(gv, gv);
                    fma2(a0, g2, wn2[k][0]);
                    fma2(a1, g2, wn2[k][1]);
                }
                float v0, v1, v2, v3;
                unpack2(a0, v0, v1); unpack2(a1, v2, v3);
                uint32_t* dst = (uint32_t*)(Pb + p * TSTRIDE + cl * 16 + mq * 4);
                *(uint4*)dst = make_uint4(cvt_tf32(v0), cvt_tf32(v1),
                                          cvt_tf32(v2), cvt_tf32(v3));
            }

            // ---- W convert + store [o][f] (from prefetched regs) ----
            {
                uint32_t* dst = (uint32_t*)(Wb + ow * TSTRIDE + fq);
                *(uint4*)(dst + 0) = make_uint4(cvt_tf32(wv[0].x), cvt_tf32(wv[0].y),
                                                cvt_tf32(wv[0].z), cvt_tf32(wv[0].w));
                *(uint4*)(dst + 4) = make_uint4(cvt_tf32(wv[1].x), cvt_tf32(wv[1].y),
                                                cvt_tf32(wv[1].z), cvt_tf32(wv[1].w));
            }

            // ---- prefetch W for next chunk (hides LDG under sync+MMA) ----
            if (cg + 1 < NCHUNK) loadW(cg + 1, wv);

            // ---- gather next gidx into other buffer (hidden behind ~3 chunks) ----
            if (cl2 == 0 && gidx < 8) gather(gidx + 1, gbuf ^ 1);

            __syncthreads();

            // ---- ldmatrix + 32 HMMA per warp ----
            #pragma unroll
            for (int ks = 0; ks < 4; ++ks) {
                uint32_t a0r[4], a1r[4];
                ldsm4(a0r, aBase + bufoff + ks * 32);
                ldsm4(a1r, aBase + bufoff + 16 * TSTRIDE * 4 + ks * 32);
                #pragma unroll
                for (int np = 0; np < 2; ++np) {
                    uint32_t b[4];
                    ldsm4(b, bBase + bufoff + np * 16 * TSTRIDE * 4 + ks * 32);
                    mma8(acc[0][np * 2 + 0], a0r, b[0], b[1]);
                    mma8(acc[0][np * 2 + 1], a0r, b[2], b[3]);
                    mma8(acc[1][np * 2 + 0], a1r, b[0], b[1]);
                    mma8(acc[1][np * 2 + 1], a1r, b[2], b[3]);
                }
            }
            // no trailing sync: double-buffered tiles; next chunk's sync orders
            // MMA(c) before tile-buffer reuse at chunk c+2.
        }
    }

    // ---- epilogue: bias + store (each warp 32p x 32o) ----
    #pragma unroll
    for (int mt = 0; mt < 2; ++mt) {
        int r = wm * 32 + mt * 16 + (l >> 2);
        #pragma unroll
        for (int nt = 0; nt < 4; ++nt) {
            int o  = wn * 32 + nt * 8 + 2 * (l & 3);
            float b0 = sm[OFF_BIAS + o], b1 = sm[OFF_BIAS + o + 1];
            int pid = base + r;
            if (pid < NPTS) {
                float2 v = make_float2(acc[mt][nt][0] + b0, acc[mt][nt][1] + b1);
                *(float2*)(out + (size_t)pid * 128 + o) = v;
            }
            int pid2 = base + r + 8;
            if (pid2 < NPTS) {
                float2 v = make_float2(acc[mt][nt][2] + b0, acc[mt][nt][3] + b1);
                *(float2*)(out + (size_t)pid2 * 128 + o) = v;
            }
        }
    }
}

extern "C" void kernel_launch(void* const* d_in, const int* in_sizes, int n_in,
                              void* d_out, int out_size) {
    const float* xin  = (const float*)d_in[0];
    const int*   nbr  = (const int*)d_in[1];
    const float* wng  = (const float*)d_in[2];
    const float* addf = (const float*)d_in[3];
    const float* W    = (const float*)d_in[4];
    const float* bias = (const float*)d_in[5];
    float*       out  = (float*)d_out;

    cudaFuncSetAttribute(pcl_kernel,
                         cudaFuncAttributeMaxDynamicSharedMemorySize, SMEM_BYTES);

    pcl_kernel<<<GRID, THREADS, SMEM_BYTES>>>(xin, nbr, wng, addf, W, bias, out);
}